// round 2
// baseline (speedup 1.0000x reference)
#include <cuda_runtime.h>
#include <math.h>

#define NT 10
#define NL 16
#define NNODES 31
#define DD 256
#define BB 4096
#define NCOMBO 160          // NT * NL distinct (tree, leaf) sequences
#define NODES_TOT 310       // NT * NNODES distinct embedding nodes
#define G4 1024             // 4 * D gate width

// Static scratch (no allocations allowed)
__device__ __align__(16) float g_XG[NODES_TOT * G4];     // 1.27 MB
__device__ __align__(16) float g_H[2][NCOMBO * DD];      // ping-pong h
__device__ __align__(16) float g_C[2][NCOMBO * DD];      // ping-pong c

__device__ __forceinline__ float sigf(float x) { return 1.0f / (1.0f + __expf(-x)); }

// ---------------------------------------------------------------------------
// XG[n][j] = sum_d emb[n][d] * W_ih[j][d] + b_ih[j] + b_hh[j]
// M=310 (padded 320), N=1024, K=256. BM=32, BN=64, BK=64. grid(16,10), 256thr.
// ---------------------------------------------------------------------------
__global__ void xg_kernel(const float* __restrict__ emb,
                          const float* __restrict__ W_ih,
                          const float* __restrict__ b_ih,
                          const float* __restrict__ b_hh) {
    __shared__ float sE[32][65];
    __shared__ float sW[64][65];
    const int n0 = blockIdx.x * 64;
    const int m0 = blockIdx.y * 32;
    const int tid = threadIdx.x;
    const int tm = tid >> 4, tn = tid & 15;
    float acc[2][4] = {};

    for (int k0 = 0; k0 < 256; k0 += 64) {
        // E tile: 32x64 = 512 float4
        for (int i = tid; i < 512; i += 256) {
            int r = i >> 4, c4 = i & 15;
            int gm = m0 + r;
            float4 v = (gm < NODES_TOT)
                     ? *(const float4*)(emb + gm * 256 + k0 + c4 * 4)
                     : make_float4(0.f, 0.f, 0.f, 0.f);
            sE[r][c4*4+0] = v.x; sE[r][c4*4+1] = v.y;
            sE[r][c4*4+2] = v.z; sE[r][c4*4+3] = v.w;
        }
        // W tile: 64x64 = 1024 float4
        for (int i = tid; i < 1024; i += 256) {
            int r = i >> 4, c4 = i & 15;
            float4 v = *(const float4*)(W_ih + (n0 + r) * 256 + k0 + c4 * 4);
            sW[r][c4*4+0] = v.x; sW[r][c4*4+1] = v.y;
            sW[r][c4*4+2] = v.z; sW[r][c4*4+3] = v.w;
        }
        __syncthreads();
        #pragma unroll
        for (int k = 0; k < 64; ++k) {
            float e0 = sE[tm*2+0][k], e1 = sE[tm*2+1][k];
            float w0 = sW[tn*4+0][k], w1 = sW[tn*4+1][k];
            float w2 = sW[tn*4+2][k], w3 = sW[tn*4+3][k];
            acc[0][0] += e0*w0; acc[0][1] += e0*w1; acc[0][2] += e0*w2; acc[0][3] += e0*w3;
            acc[1][0] += e1*w0; acc[1][1] += e1*w1; acc[1][2] += e1*w2; acc[1][3] += e1*w3;
        }
        __syncthreads();
    }
    #pragma unroll
    for (int mm = 0; mm < 2; ++mm) {
        int m = m0 + tm*2 + mm;
        if (m >= NODES_TOT) continue;
        #pragma unroll
        for (int nn = 0; nn < 4; ++nn) {
            int n = n0 + tn*4 + nn;
            g_XG[m * G4 + n] = acc[mm][nn] + b_ih[n] + b_hh[n];
        }
    }
}

// ---------------------------------------------------------------------------
// Step 0: h0 = 0, so gates come straight from XG at the root node (tree*31).
// ---------------------------------------------------------------------------
__global__ void step0_kernel() {
    int idx = blockIdx.x * blockDim.x + threadIdx.x;   // 160*256 = 40960
    int combo = idx >> 8;
    int d = idx & 255;
    int tree = combo >> 4;
    const float* xg = g_XG + (tree * NNODES) * G4;
    float gi = xg[d], gg = xg[512 + d], go = xg[768 + d];
    float c = sigf(gi) * tanhf(gg);               // sig(f)*0 term vanishes
    float h = sigf(go) * tanhf(c);
    g_H[0][idx] = h;
    g_C[0][idx] = c;
}

// ---------------------------------------------------------------------------
// Steps 1..4: for each combo, gates = XG[node_t] + h_prev @ W_hh^T, then LSTM
// update. Block = 20 combos x 16 d's (64 gate-rows). grid(16,8)=128 blocks
// (single wave on 148 SMs), 320 threads (10 warps). Warp = 2 combos x 64
// rows; lane owns rows {lane, lane+32}. h reads are smem broadcasts, W reads
// are conflict-free (pitch 65). shfl_xor(16) reunites the 4 gates per (c,d).
// ---------------------------------------------------------------------------
__global__ __launch_bounds__(320) void step_kernel(int t, int bin, int bout,
                                                   const float* __restrict__ W_hh) {
    __shared__ __align__(16) float sh[20 * 256];   // h tile for 20 combos
    __shared__ float sW[64][65];                   // 64 gate rows x 64 k
    const int tid = threadIdx.x;
    const int dx = blockIdx.x;        // d-tile: d0 = dx*16
    const int cy = blockIdx.y;        // combo-tile: combos cy*20 .. cy*20+19
    const int d0 = dx << 4;
    const float* Hin = g_H[bin];
    const float* Cin = g_C[bin];

    // Load h tile (20x256 = 1280 float4), coalesced.
    {
        const float4* src = (const float4*)(Hin + cy * 20 * 256);
        float4* dst = (float4*)sh;
        for (int i = tid; i < 1280; i += 320) dst[i] = src[i];
    }

    const int w = tid >> 5, lane = tid & 31;
    const int lc0 = 2 * w, lc1 = lc0 + 1;          // local combos in tile
    const int c0 = cy * 20 + lc0, c1 = c0 + 1;
    const int ra = lane, rb = lane + 32;

    float a00 = 0.f, a01 = 0.f, a10 = 0.f, a11 = 0.f;
    const float4* sh4 = (const float4*)sh;

    for (int k0 = 0; k0 < 256; k0 += 64) {
        // Load W rows: row r -> gate=(r>>4), dl=(r&15), j = gate*256 + d0 + dl
        for (int i = tid; i < 64 * 16; i += 320) {
            int r = i >> 4, c4 = i & 15;
            int j = ((r >> 4) << 8) + d0 + (r & 15);
            float4 v = *(const float4*)(W_hh + j * 256 + k0 + c4 * 4);
            sW[r][c4*4+0] = v.x; sW[r][c4*4+1] = v.y;
            sW[r][c4*4+2] = v.z; sW[r][c4*4+3] = v.w;
        }
        __syncthreads();
        int kb = k0 >> 2;
        #pragma unroll
        for (int k4 = 0; k4 < 16; ++k4) {
            float4 h0 = sh4[lc0 * 64 + kb + k4];   // broadcast within warp
            float4 h1 = sh4[lc1 * 64 + kb + k4];
            float wa0 = sW[ra][k4*4+0], wa1 = sW[ra][k4*4+1];
            float wa2 = sW[ra][k4*4+2], wa3 = sW[ra][k4*4+3];
            float wb0 = sW[rb][k4*4+0], wb1 = sW[rb][k4*4+1];
            float wb2 = sW[rb][k4*4+2], wb3 = sW[rb][k4*4+3];
            a00 += h0.x*wa0; a00 += h0.y*wa1; a00 += h0.z*wa2; a00 += h0.w*wa3;
            a01 += h0.x*wb0; a01 += h0.y*wb1; a01 += h0.z*wb2; a01 += h0.w*wb3;
            a10 += h1.x*wa0; a10 += h1.y*wa1; a10 += h1.z*wa2; a10 += h1.w*wa3;
            a11 += h1.x*wb0; a11 += h1.y*wb1; a11 += h1.z*wb2; a11 += h1.w*wb3;
        }
        __syncthreads();
    }

    // Gate exchange: lane<16 holds (gate0, gate2) for both combos; lane>=16
    // holds (gate1, gate3). lane<16 finalizes c0; lane>=16 finalizes c1.
    float sA = (lane & 16) ? a00 : a10;
    float sB = (lane & 16) ? a01 : a11;
    float rA = __shfl_xor_sync(0xffffffffu, sA, 16);
    float rB = __shfl_xor_sync(0xffffffffu, sB, 16);

    float gi, gf, gg, go;
    int c;
    if (lane & 16) { c = c1; gi = rA;  gf = a10; gg = rB;  go = a11; }
    else           { c = c0; gi = a00; gf = rA;  gg = a01; go = rB;  }

    int dl = lane & 15;
    int d = d0 + dl;
    int tree = c >> 4, leaf = c & 15;
    int local = ((1 << t) - 1) + (leaf >> (4 - t));   // heap-indexed path node
    const float* xg = g_XG + (tree * NNODES + local) * G4;
    gi += xg[d]; gf += xg[256 + d]; gg += xg[512 + d]; go += xg[768 + d];

    float cp = Cin[c * 256 + d];
    float cn = sigf(gf) * cp + sigf(gi) * tanhf(gg);
    float hn = sigf(go) * tanhf(cn);
    g_C[bout][c * 256 + d] = cn;
    g_H[bout][c * 256 + d] = hn;
}

// ---------------------------------------------------------------------------
// Gather: one warp per (b, tree). Argmax of the one-hot via ballot, then copy
// 256 floats (2 float4 per lane) from the 160-row H table (L2-resident).
// ---------------------------------------------------------------------------
__global__ void gather_kernel(const float* __restrict__ cross,
                              float* __restrict__ out) {
    int gw = (blockIdx.x * blockDim.x + threadIdx.x) >> 5;
    int lane = threadIdx.x & 31;
    if (gw >= BB * NT) return;
    int b = gw / NT;
    int tr = gw - b * NT;
    float v = 0.f;
    if (lane < NL) v = cross[b * (NT * NL) + tr * NL + lane];
    unsigned m = __ballot_sync(0xffffffffu, v > 0.5f);
    int leaf = __ffs(m) - 1;
    const float4* src = (const float4*)(g_H[0] + (tr * NL + leaf) * 256);
    float4* dst = (float4*)(out + (size_t)gw * 256);
    dst[lane]      = src[lane];
    dst[lane + 32] = src[lane + 32];
}

// ---------------------------------------------------------------------------
extern "C" void kernel_launch(void* const* d_in, const int* in_sizes, int n_in,
                              void* d_out, int out_size) {
    const float* cross = (const float*)d_in[0];
    const float* emb   = (const float*)d_in[1];
    const float* W_ih  = (const float*)d_in[2];
    const float* W_hh  = (const float*)d_in[3];
    const float* b_ih  = (const float*)d_in[4];
    const float* b_hh  = (const float*)d_in[5];
    float* out = (float*)d_out;

    xg_kernel<<<dim3(16, 10), 256>>>(emb, W_ih, b_ih, b_hh);
    step0_kernel<<<160, 256>>>();
    step_kernel<<<dim3(16, 8), 320>>>(1, 0, 1, W_hh);
    step_kernel<<<dim3(16, 8), 320>>>(2, 1, 0, W_hh);
    step_kernel<<<dim3(16, 8), 320>>>(3, 0, 1, W_hh);
    step_kernel<<<dim3(16, 8), 320>>>(4, 1, 0, W_hh);
    gather_kernel<<<(BB * NT * 32 + 255) / 256, 256>>>(cross, out);
}

// round 3
// speedup vs baseline: 1.0365x; 1.0365x over previous
#include <cuda_runtime.h>
#include <math.h>

typedef unsigned long long ull;

#define NT 10
#define NL 16
#define NNODES 31
#define BB 4096
#define G4 1024
#define NBLOCKS 128
#define NTHR 320

// smem layout in floats
#define PW 260                      // W pitch (16B-aligned rows, conflict-free LDS.128)
#define OFF_W 0                     // 64 rows x PW
#define OFF_H (64 * PW)             // 20 combos x 256
#define OFF_R (OFF_H + 20 * 256)    // 20 combos x 64 gate-rows staging
#define SMEM_FLOATS (OFF_R + 20 * 64)
#define SMEM_BYTES (SMEM_FLOATS * 4)

__device__ __align__(16) float g_XG[310 * G4];
__device__ __align__(16) float g_H[2][160 * 256];
__device__ unsigned g_count = 0;
__device__ unsigned g_gen = 0;

__device__ __forceinline__ float sigf(float x) { return 1.0f / (1.0f + __expf(-x)); }

__device__ __forceinline__ void fma2(ull& d, ull a, ull b) {
    asm("fma.rn.f32x2 %0, %1, %2, %0;" : "+l"(d) : "l"(a), "l"(b));
}

__device__ __forceinline__ float sum2(ull v) {
    float2 f = *(float2*)&v;
    return f.x + f.y;
}

// Software grid barrier (all NBLOCKS resident by construction).
__device__ __forceinline__ void gridbar(unsigned& target) {
    __syncthreads();
    if (threadIdx.x == 0) {
        target += 1;
        __threadfence();
        if (atomicAdd(&g_count, 1) == NBLOCKS - 1) {
            g_count = 0;
            __threadfence();
            atomicAdd(&g_gen, 1);
        } else {
            while ((int)(*(volatile unsigned*)&g_gen - target) < 0) __nanosleep(32);
            __threadfence();
        }
    }
    __syncthreads();
}

// ---------------------------------------------------------------------------
// XG[n][j] = emb[n] . W_ih[j] + b_ih[j] + b_hh[j]   (M=310, N=1024, K=256)
// ---------------------------------------------------------------------------
__global__ void xg_kernel(const float* __restrict__ emb,
                          const float* __restrict__ W_ih,
                          const float* __restrict__ b_ih,
                          const float* __restrict__ b_hh) {
    __shared__ float sE[32][65];
    __shared__ float sW[64][65];
    const int n0 = blockIdx.x * 64;
    const int m0 = blockIdx.y * 32;
    const int tid = threadIdx.x;
    const int tm = tid >> 4, tn = tid & 15;
    float acc[2][4] = {};

    for (int k0 = 0; k0 < 256; k0 += 64) {
        for (int i = tid; i < 512; i += 256) {
            int r = i >> 4, c4 = i & 15;
            int gm = m0 + r;
            float4 v = (gm < 310)
                     ? *(const float4*)(emb + gm * 256 + k0 + c4 * 4)
                     : make_float4(0.f, 0.f, 0.f, 0.f);
            sE[r][c4*4+0] = v.x; sE[r][c4*4+1] = v.y;
            sE[r][c4*4+2] = v.z; sE[r][c4*4+3] = v.w;
        }
        for (int i = tid; i < 1024; i += 256) {
            int r = i >> 4, c4 = i & 15;
            float4 v = *(const float4*)(W_ih + (n0 + r) * 256 + k0 + c4 * 4);
            sW[r][c4*4+0] = v.x; sW[r][c4*4+1] = v.y;
            sW[r][c4*4+2] = v.z; sW[r][c4*4+3] = v.w;
        }
        __syncthreads();
        #pragma unroll
        for (int k = 0; k < 64; ++k) {
            float e0 = sE[tm*2+0][k], e1 = sE[tm*2+1][k];
            float w0 = sW[tn*4+0][k], w1 = sW[tn*4+1][k];
            float w2 = sW[tn*4+2][k], w3 = sW[tn*4+3][k];
            acc[0][0] += e0*w0; acc[0][1] += e0*w1; acc[0][2] += e0*w2; acc[0][3] += e0*w3;
            acc[1][0] += e1*w0; acc[1][1] += e1*w1; acc[1][2] += e1*w2; acc[1][3] += e1*w3;
        }
        __syncthreads();
    }
    #pragma unroll
    for (int mm = 0; mm < 2; ++mm) {
        int m = m0 + tm*2 + mm;
        if (m >= 310) continue;
        #pragma unroll
        for (int nn = 0; nn < 4; ++nn) {
            int n = n0 + tn*4 + nn;
            g_XG[m * G4 + n] = acc[mm][nn] + b_ih[n] + b_hh[n];
        }
    }
}

// ---------------------------------------------------------------------------
// Persistent LSTM + gather. Grid (16,8)=128 blocks, 320 thr, 1 block/SM.
// Block (dx,cy): d-slice d0=dx*16 (64 gate-rows), combos cy*20..+19.
// W_hh slice cached in smem once; C in registers; h via L2 (ldcg/stcg).
// Warp tiling: rg=w&1 (rows rg*32+lane), cg=w>>1 (combos cg*4..+3).
// ---------------------------------------------------------------------------
__global__ void __launch_bounds__(NTHR, 1)
lstm_kernel(const float* __restrict__ W_hh,
            const float* __restrict__ cross,
            float* __restrict__ out) {
    extern __shared__ __align__(16) float sm[];
    float* sW = sm + OFF_W;
    float* sh = sm + OFF_H;
    float* sR = sm + OFF_R;

    const int tid = threadIdx.x;
    const int dx = blockIdx.x;          // 0..15
    const int cy = blockIdx.y;          // 0..7
    const int d0 = dx << 4;

    unsigned target = 0;
    if (tid == 0) target = *((volatile unsigned*)&g_gen);

    // Cache W_hh slice: row r (0..63): j = (r>>4)*256 + d0 + (r&15), k=0..255.
    for (int i = tid; i < 4096; i += NTHR) {
        int row = i >> 6, q = i & 63;
        int j = ((row >> 4) << 8) + d0 + (row & 15);
        *(float4*)(sW + row * PW + q * 4) = ((const float4*)W_hh)[j * 64 + q];
    }

    // Per-thread output ownership: combo lc=tid/16, d-lane dl=tid%16.
    const int lc = tid >> 4, dl = tid & 15;
    const int c = cy * 20 + lc;            // global combo 0..159
    const int d = d0 + dl;                 // 0..255
    const int tree = c >> 4, leaf = c & 15;

    // ---- Step 0 (h0 = c0 = 0): gates straight from XG at root node ----
    float cst;
    {
        const float* xg = g_XG + (tree * NNODES) * G4;
        float gi = xg[d], gg = xg[512 + d], go = xg[768 + d];
        cst = sigf(gi) * tanhf(gg);
        float h = sigf(go) * tanhf(cst);
        __stcg(&g_H[0][c * 256 + d], h);
    }
    gridbar(target);

    // ---- Steps 1..4 ----
    const int w = tid >> 5, lane = tid & 31;
    const int rg = w & 1, cg = w >> 1;     // row-group, combo-group
    const int r = rg * 32 + lane;          // gate-row 0..63
    const float* Wr = sW + r * PW;
    const float* hb = sh + (cg * 4) * 256;

    #pragma unroll
    for (int t = 1; t <= 4; ++t) {
        const int bin = 1 - (t & 1), bout = t & 1;

        // Load h tile (20 x 256) from L2, bypassing L1.
        {
            const float4* src = (const float4*)(g_H[bin] + cy * 5120);
            float4* dst = (float4*)sh;
            for (int i = tid; i < 1280; i += NTHR) dst[i] = __ldcg(src + i);
        }
        __syncthreads();

        // acc[c] = dot(W row r, h combo cg*4+c), f32x2-packed over k.
        ull a0 = 0, a1 = 0, a2 = 0, a3 = 0;
        #pragma unroll 16
        for (int kq = 0; kq < 64; ++kq) {
            ulonglong2 wv = *(const ulonglong2*)(Wr + kq * 4);
            ulonglong2 h0 = *(const ulonglong2*)(hb + 0 * 256 + kq * 4);
            ulonglong2 h1 = *(const ulonglong2*)(hb + 1 * 256 + kq * 4);
            ulonglong2 h2 = *(const ulonglong2*)(hb + 2 * 256 + kq * 4);
            ulonglong2 h3 = *(const ulonglong2*)(hb + 3 * 256 + kq * 4);
            fma2(a0, wv.x, h0.x); fma2(a0, wv.y, h0.y);
            fma2(a1, wv.x, h1.x); fma2(a1, wv.y, h1.y);
            fma2(a2, wv.x, h2.x); fma2(a2, wv.y, h2.y);
            fma2(a3, wv.x, h3.x); fma2(a3, wv.y, h3.y);
        }
        sR[(cg * 4 + 0) * 64 + r] = sum2(a0);
        sR[(cg * 4 + 1) * 64 + r] = sum2(a1);
        sR[(cg * 4 + 2) * 64 + r] = sum2(a2);
        sR[(cg * 4 + 3) * 64 + r] = sum2(a3);
        __syncthreads();

        // Finalize my (c, d): gates = sR + XG[node_t], LSTM update.
        int local = ((1 << t) - 1) + (leaf >> (4 - t));
        const float* xg = g_XG + (tree * NNODES + local) * G4;
        float gi = sR[lc * 64 +  0 + dl] + xg[d];
        float gf = sR[lc * 64 + 16 + dl] + xg[256 + d];
        float gg = sR[lc * 64 + 32 + dl] + xg[512 + d];
        float go = sR[lc * 64 + 48 + dl] + xg[768 + d];
        cst = sigf(gf) * cst + sigf(gi) * tanhf(gg);
        float h = sigf(go) * tanhf(cst);
        __stcg(&g_H[bout][c * 256 + d], h);

        gridbar(target);
    }

    // ---- Gather: final H is in g_H[0] (L2-resident). 320 rows per block. ----
    const int bid = cy * 16 + dx;          // 0..127
    for (int i = 0; i < 32; ++i) {
        int gw = bid * 320 + w * 32 + i;   // (b, tree) row index, 0..40959
        int b = gw / NT;
        int tr = gw - b * NT;
        float v = 0.f;
        if (lane < NL) v = __ldg(&cross[b * (NT * NL) + tr * NL + lane]);
        unsigned m = __ballot_sync(0xffffffffu, v > 0.5f);
        int lf = __ffs(m) - 1;
        const float4* src = (const float4*)(g_H[0] + (tr * NL + lf) * 256);
        float4* dst = (float4*)(out + (size_t)gw * 256);
        dst[lane]      = __ldcg(src + lane);
        dst[lane + 32] = __ldcg(src + lane + 32);
    }
}

// ---------------------------------------------------------------------------
extern "C" void kernel_launch(void* const* d_in, const int* in_sizes, int n_in,
                              void* d_out, int out_size) {
    const float* cross = (const float*)d_in[0];
    const float* emb   = (const float*)d_in[1];
    const float* W_ih  = (const float*)d_in[2];
    const float* W_hh  = (const float*)d_in[3];
    const float* b_ih  = (const float*)d_in[4];
    const float* b_hh  = (const float*)d_in[5];
    float* out = (float*)d_out;

    static int attr_done = 0;
    if (!attr_done) {
        cudaFuncSetAttribute(lstm_kernel,
                             cudaFuncAttributeMaxDynamicSharedMemorySize,
                             SMEM_BYTES);
        attr_done = 1;
    }

    xg_kernel<<<dim3(16, 10), 256>>>(emb, W_ih, b_ih, b_hh);
    lstm_kernel<<<dim3(16, 8), NTHR, SMEM_BYTES>>>(W_hh, cross, out);
}

// round 4
// speedup vs baseline: 1.2138x; 1.1710x over previous
#include <cuda_runtime.h>
#include <math.h>

typedef unsigned long long ull;

#define NT 10
#define NL 16
#define NNODES 31
#define BB 4096
#define G4 1024
#define NTHR 512

// smem layout in floats
#define PW 260                       // W row pitch (16B aligned, conflict-free)
#define PR 80                        // sR combo pitch (conflict-free finalize)
#define OFF_W 0                      // 64 rows x PW
#define OFF_H (64 * PW)              // 20 combos x 256
#define OFF_R (OFF_H + 20 * 256)     // 4 kslices x 20 combos x PR
#define SMEM_FLOATS (OFF_R + 4 * 20 * PR)
#define SMEM_BYTES (SMEM_FLOATS * 4)

__device__ __align__(16) float g_XG[310 * G4];
__device__ __align__(16) float g_H[2][160 * 256];
__device__ int g_leaf[BB * NT];
__device__ unsigned g_cnt[8 * 32];   // per-cy barrier, 128B-padded
__device__ unsigned g_gen[8 * 32];

__device__ __forceinline__ float sigf(float x) { return 1.0f / (1.0f + __expf(-x)); }

__device__ __forceinline__ void fma2(ull& d, ull a, ull b) {
    asm("fma.rn.f32x2 %0, %1, %2, %0;" : "+l"(d) : "l"(a), "l"(b));
}
__device__ __forceinline__ float sum2(ull v) {
    float2 f = *(float2*)&v;
    return f.x + f.y;
}

// Barrier across the 16 dx-blocks sharing one cy (all resident).
__device__ __forceinline__ void cybar(int cy, unsigned& target) {
    __syncthreads();
    if (threadIdx.x == 0) {
        target += 1;
        __threadfence();
        if (atomicAdd(&g_cnt[cy * 32], 1) == 15) {
            g_cnt[cy * 32] = 0;
            __threadfence();
            atomicAdd(&g_gen[cy * 32], 1);
        } else {
            while ((int)(*(volatile unsigned*)&g_gen[cy * 32] - target) < 0)
                __nanosleep(32);
            __threadfence();
        }
    }
    __syncthreads();
}

// ---------------------------------------------------------------------------
// XG[n][j] = emb[n] . W_ih[j] + b_ih[j] + b_hh[j]   (M=310, N=1024, K=256)
// ---------------------------------------------------------------------------
__global__ void xg_kernel(const float* __restrict__ emb,
                          const float* __restrict__ W_ih,
                          const float* __restrict__ b_ih,
                          const float* __restrict__ b_hh) {
    __shared__ float sE[32][65];
    __shared__ float sW[64][65];
    const int n0 = blockIdx.x * 64;
    const int m0 = blockIdx.y * 32;
    const int tid = threadIdx.x;
    const int tm = tid >> 4, tn = tid & 15;
    float acc[2][4] = {};

    for (int k0 = 0; k0 < 256; k0 += 64) {
        for (int i = tid; i < 512; i += 256) {
            int r = i >> 4, c4 = i & 15;
            int gm = m0 + r;
            float4 v = (gm < 310)
                     ? *(const float4*)(emb + gm * 256 + k0 + c4 * 4)
                     : make_float4(0.f, 0.f, 0.f, 0.f);
            sE[r][c4*4+0] = v.x; sE[r][c4*4+1] = v.y;
            sE[r][c4*4+2] = v.z; sE[r][c4*4+3] = v.w;
        }
        for (int i = tid; i < 1024; i += 256) {
            int r = i >> 4, c4 = i & 15;
            float4 v = *(const float4*)(W_ih + (n0 + r) * 256 + k0 + c4 * 4);
            sW[r][c4*4+0] = v.x; sW[r][c4*4+1] = v.y;
            sW[r][c4*4+2] = v.z; sW[r][c4*4+3] = v.w;
        }
        __syncthreads();
        #pragma unroll
        for (int k = 0; k < 64; ++k) {
            float e0 = sE[tm*2+0][k], e1 = sE[tm*2+1][k];
            float w0 = sW[tn*4+0][k], w1 = sW[tn*4+1][k];
            float w2 = sW[tn*4+2][k], w3 = sW[tn*4+3][k];
            acc[0][0] += e0*w0; acc[0][1] += e0*w1; acc[0][2] += e0*w2; acc[0][3] += e0*w3;
            acc[1][0] += e1*w0; acc[1][1] += e1*w1; acc[1][2] += e1*w2; acc[1][3] += e1*w3;
        }
        __syncthreads();
    }
    #pragma unroll
    for (int mm = 0; mm < 2; ++mm) {
        int m = m0 + tm*2 + mm;
        if (m >= 310) continue;
        #pragma unroll
        for (int nn = 0; nn < 4; ++nn) {
            int n = n0 + tn*4 + nn;
            g_XG[m * G4 + n] = acc[mm][nn] + b_ih[n] + b_hh[n];
        }
    }
}

// ---------------------------------------------------------------------------
// Persistent LSTM. Grid (16,8)=128 blocks, 512 thr (16 warps), 1 block/SM.
// Block (dx,cy): 64 gate-rows for d-slice d0=dx*16, combos cy*20..+19.
// Warp tile: 32 rows (rg) x 10 combos (cs) x 64-K slice (ks). sR holds 4
// K-partials, summed in the finalize. C stays in registers; h via L2.
// ---------------------------------------------------------------------------
__global__ void __launch_bounds__(NTHR, 1)
lstm_kernel(const float* __restrict__ W_hh) {
    extern __shared__ __align__(16) float sm[];
    float* sW = sm + OFF_W;
    float* sh = sm + OFF_H;
    float* sR = sm + OFF_R;

    const int tid = threadIdx.x;
    const int dx = blockIdx.x;      // 0..15
    const int cy = blockIdx.y;      // 0..7
    const int d0 = dx << 4;

    unsigned target = 0;
    if (tid == 0) target = *((volatile unsigned*)&g_gen[cy * 32]);

    // Cache W_hh slice: row r: j = (r>>4)*256 + d0 + (r&15), k = 0..255.
    for (int i = tid; i < 4096; i += NTHR) {
        int row = i >> 6, q = i & 63;
        int j = ((row >> 4) << 8) + d0 + (row & 15);
        *(float4*)(sW + row * PW + q * 4) = ((const float4*)W_hh)[j * 64 + q];
    }

    // Finalize-thread ownership (tid < 320): combo lc, d-lane dl.
    const int lc = tid >> 4, dl = tid & 15;
    const int c = cy * 20 + lc;
    const int d = d0 + dl;
    const int tree = c >> 4, leaf = c & 15;

    // ---- Step 0 (h0 = c0 = 0) ----
    float cst = 0.f;
    if (tid < 320) {
        const float* xg = g_XG + (tree * NNODES) * G4;
        float gi = xg[d], gg = xg[512 + d], go = xg[768 + d];
        cst = sigf(gi) * tanhf(gg);
        float h = sigf(go) * tanhf(cst);
        __stcg(&g_H[0][c * 256 + d], h);
    }
    cybar(cy, target);

    // Warp tiling for the recurrent GEMM.
    const int w = tid >> 5, lane = tid & 31;
    const int rg = w & 1;            // row group: rows rg*32+lane
    const int cs = (w >> 1) & 1;     // combo half: combos cs*10..+9
    const int ks = w >> 2;           // K slice: k = ks*64..+63
    const int r = rg * 32 + lane;
    const float* Wr = sW + r * PW + ks * 64;
    const float* hb = sh + cs * 10 * 256 + ks * 64;
    float* rb = sR + ks * (20 * PR) + cs * 10 * PR;

    #pragma unroll
    for (int t = 1; t <= 4; ++t) {
        const int bin = 1 - (t & 1), bout = t & 1;

        // Load h tile (20 x 256) from L2.
        {
            const float4* src = (const float4*)(g_H[bin] + cy * 5120);
            float4* dst = (float4*)sh;
            for (int i = tid; i < 1280; i += NTHR) dst[i] = __ldcg(src + i);
        }
        __syncthreads();

        ull acc[10] = {};
        #pragma unroll
        for (int kq = 0; kq < 16; ++kq) {
            ulonglong2 wv = *(const ulonglong2*)(Wr + kq * 4);
            #pragma unroll
            for (int i = 0; i < 10; ++i) {
                ulonglong2 hv = *(const ulonglong2*)(hb + i * 256 + kq * 4);
                fma2(acc[i], wv.x, hv.x);
                fma2(acc[i], wv.y, hv.y);
            }
        }
        #pragma unroll
        for (int i = 0; i < 10; ++i) rb[i * PR + r] = sum2(acc[i]);
        __syncthreads();

        if (tid < 320) {
            int local = ((1 << t) - 1) + (leaf >> (4 - t));
            const float* xg = g_XG + (tree * NNODES + local) * G4;
            const float* rr = sR + lc * PR + dl;
            float gi = rr[0]  + rr[1600]      + rr[3200]      + rr[4800];
            float gf = rr[16] + rr[1600 + 16] + rr[3200 + 16] + rr[4800 + 16];
            float gg = rr[32] + rr[1600 + 32] + rr[3200 + 32] + rr[4800 + 32];
            float go = rr[48] + rr[1600 + 48] + rr[3200 + 48] + rr[4800 + 48];
            gi += xg[d]; gf += xg[256 + d]; gg += xg[512 + d]; go += xg[768 + d];
            cst = sigf(gf) * cst + sigf(gi) * tanhf(gg);
            float h = sigf(go) * tanhf(cst);
            __stcg(&g_H[bout][c * 256 + d], h);
        }
        if (t < 4) cybar(cy, target);
    }
}

// ---------------------------------------------------------------------------
// Leaf index per (b, tree) row: ballot over 16-lane groups.
// ---------------------------------------------------------------------------
__global__ void leaf_kernel(const float* __restrict__ cross) {
    int gid = blockIdx.x * 256 + threadIdx.x;    // 0..655359
    float v = cross[gid];
    unsigned m = __ballot_sync(0xffffffffu, v > 0.5f);
    int lane = threadIdx.x & 31;
    unsigned m16 = (m >> (lane & 16)) & 0xFFFFu;
    if ((lane & 15) == 0) g_leaf[gid >> 4] = __ffs(m16) - 1;
}

// ---------------------------------------------------------------------------
// Gather: one thread per output float4 (2.62M threads) -> latency fully
// hidden, bound by L2 read+write throughput.
// ---------------------------------------------------------------------------
__global__ void gather_kernel(float4* __restrict__ out) {
    int gid = blockIdx.x * 256 + threadIdx.x;    // 0..2621439
    int row = gid >> 6, q = gid & 63;
    int lf = g_leaf[row];
    int tr = row - (row / NT) * NT;
    const float4* H4 = (const float4*)g_H[0];
    out[gid] = __ldg(H4 + ((tr << 4) + lf) * 64 + q);
}

// ---------------------------------------------------------------------------
extern "C" void kernel_launch(void* const* d_in, const int* in_sizes, int n_in,
                              void* d_out, int out_size) {
    const float* cross = (const float*)d_in[0];
    const float* emb   = (const float*)d_in[1];
    const float* W_ih  = (const float*)d_in[2];
    const float* W_hh  = (const float*)d_in[3];
    const float* b_ih  = (const float*)d_in[4];
    const float* b_hh  = (const float*)d_in[5];

    static int attr_done = 0;
    if (!attr_done) {
        cudaFuncSetAttribute(lstm_kernel,
                             cudaFuncAttributeMaxDynamicSharedMemorySize,
                             SMEM_BYTES);
        attr_done = 1;
    }

    xg_kernel<<<dim3(16, 10), 256>>>(emb, W_ih, b_ih, b_hh);
    leaf_kernel<<<BB * NT * NL / 256, 256>>>(cross);
    lstm_kernel<<<dim3(16, 8), NTHR, SMEM_BYTES>>>(W_hh);
    gather_kernel<<<BB * NT * 64 / 256, 256>>>((float4*)d_out);
}